// round 1
// baseline (speedup 1.0000x reference)
#include <cuda_runtime.h>
#include <math.h>

#ifndef INFINITY
#define INFINITY (1.0f/0.0f)
#endif

#define BB 8
#define SQ 512
#define SKK 1024
#define DD 1024
#define HH 16
#define DKK 64
#define FF 4096
#define NQ (BB*SQ)     /* 4096 */
#define NKV (BB*SKK)   /* 8192 */

// ------------------------- scratch (device globals; no allocs) ---------------
__device__ float g_Q[(size_t)NQ*DD];
__device__ float g_K[(size_t)NKV*DD];
__device__ float g_V[(size_t)NKV*DD];
__device__ float g_S[(size_t)BB*HH*SQ*SQ];      // self-attn scores
__device__ float g_ctx[(size_t)NQ*DD];
__device__ float g_res[(size_t)NQ*DD];
__device__ float g_x1[(size_t)NQ*DD];
__device__ float g_x2[(size_t)NQ*DD];
__device__ float g_ffh[(size_t)NQ*FF];

// ------------------------- SGEMM: C = A[MxK]*B[KxN] + bias, opt relu ---------
template<int RELU>
__global__ __launch_bounds__(256) void sgemm_bias(
    const float* __restrict__ A, const float* __restrict__ Bm,
    const float* __restrict__ bias, float* __restrict__ C,
    int M, int N, int K)
{
    __shared__ float As[16][128];   // As[k][m]
    __shared__ float Bs[16][128];   // Bs[k][n]
    const int tid = threadIdx.x;
    const int tx = tid & 15, ty = tid >> 4;
    const int mBase = blockIdx.y * 128;
    const int nBase = blockIdx.x * 128;

    float acc[8][8];
    #pragma unroll
    for (int i = 0; i < 8; i++)
        #pragma unroll
        for (int j = 0; j < 8; j++) acc[i][j] = 0.f;

    for (int k0 = 0; k0 < K; k0 += 16) {
        #pragma unroll
        for (int l = 0; l < 2; l++) {
            int s = tid * 2 + l;
            int ar = s >> 2, ak = (s & 3) * 4;
            float4 av = *(const float4*)(A + (size_t)(mBase + ar) * K + k0 + ak);
            As[ak + 0][ar] = av.x; As[ak + 1][ar] = av.y;
            As[ak + 2][ar] = av.z; As[ak + 3][ar] = av.w;
            int br = s >> 5, bn = (s & 31) * 4;
            float4 bv = *(const float4*)(Bm + (size_t)(k0 + br) * N + nBase + bn);
            *(float4*)&Bs[br][bn] = bv;
        }
        __syncthreads();
        #pragma unroll
        for (int kk = 0; kk < 16; kk++) {
            float a[8], b[8];
            *(float4*)&a[0] = *(float4*)&As[kk][ty * 8];
            *(float4*)&a[4] = *(float4*)&As[kk][ty * 8 + 4];
            *(float4*)&b[0] = *(float4*)&Bs[kk][tx * 8];
            *(float4*)&b[4] = *(float4*)&Bs[kk][tx * 8 + 4];
            #pragma unroll
            for (int i = 0; i < 8; i++)
                #pragma unroll
                for (int j = 0; j < 8; j++)
                    acc[i][j] += a[i] * b[j];
        }
        __syncthreads();
    }

    #pragma unroll
    for (int i = 0; i < 8; i++) {
        int row = mBase + ty * 8 + i;
        #pragma unroll
        for (int j = 0; j < 8; j += 4) {
            int col = nBase + tx * 8 + j;
            float4 o;
            o.x = acc[i][j + 0] + bias[col + 0];
            o.y = acc[i][j + 1] + bias[col + 1];
            o.z = acc[i][j + 2] + bias[col + 2];
            o.w = acc[i][j + 3] + bias[col + 3];
            if (RELU) {
                o.x = fmaxf(o.x, 0.f); o.y = fmaxf(o.y, 0.f);
                o.z = fmaxf(o.z, 0.f); o.w = fmaxf(o.w, 0.f);
            }
            *(float4*)(C + (size_t)row * N + col) = o;
        }
    }
}

// ------------- attention scores: S = scale * Q K^T (+ causal / kv-mask) ------
// grid: (sk/64, SQ/64, B*H). Q rows: b*SQ + i, K rows: b*sk + j, head offset h*64.
template<int CAUSAL, int MASKED>
__global__ __launch_bounds__(256) void attn_scores(
    const float* __restrict__ Q, const float* __restrict__ Kg,
    const int* __restrict__ mask, float* __restrict__ S, int sk)
{
    __shared__ float Qs[64][65];
    __shared__ float Ks[64][65];
    __shared__ int   ms[64];
    const int tid = threadIdx.x;
    const int bh = blockIdx.z, b = bh >> 4, h = bh & 15;
    const int iBase = blockIdx.y * 64, jBase = blockIdx.x * 64;

    if (CAUSAL && jBase > iBase + 63) {
        for (int s = tid; s < 64 * 64; s += 256) {
            int i = s >> 6, j = s & 63;
            S[((size_t)bh * SQ + iBase + i) * sk + jBase + j] = -INFINITY;
        }
        return;
    }

    for (int s = tid; s < 64 * 16; s += 256) {
        int r = s >> 4, d4 = (s & 15) * 4;
        float4 qv = *(const float4*)(Q + (size_t)(b * SQ + iBase + r) * DD + h * 64 + d4);
        Qs[r][d4 + 0] = qv.x; Qs[r][d4 + 1] = qv.y; Qs[r][d4 + 2] = qv.z; Qs[r][d4 + 3] = qv.w;
        float4 kv = *(const float4*)(Kg + (size_t)(b * sk + jBase + r) * DD + h * 64 + d4);
        Ks[r][d4 + 0] = kv.x; Ks[r][d4 + 1] = kv.y; Ks[r][d4 + 2] = kv.z; Ks[r][d4 + 3] = kv.w;
    }
    if (MASKED && tid < 64) ms[tid] = mask[b * SKK + jBase + tid];
    __syncthreads();

    const int i0 = (tid >> 4) * 4, j0 = (tid & 15) * 4;
    float acc[4][4];
    #pragma unroll
    for (int i = 0; i < 4; i++)
        #pragma unroll
        for (int j = 0; j < 4; j++) acc[i][j] = 0.f;

    #pragma unroll 16
    for (int d = 0; d < 64; d++) {
        float a[4], b4[4];
        #pragma unroll
        for (int i = 0; i < 4; i++) a[i] = Qs[i0 + i][d];
        #pragma unroll
        for (int j = 0; j < 4; j++) b4[j] = Ks[j0 + j][d];
        #pragma unroll
        for (int i = 0; i < 4; i++)
            #pragma unroll
            for (int j = 0; j < 4; j++)
                acc[i][j] += a[i] * b4[j];
    }

    #pragma unroll
    for (int i = 0; i < 4; i++) {
        int gi = iBase + i0 + i;
        #pragma unroll
        for (int j = 0; j < 4; j++) {
            int gj = jBase + j0 + j;
            float v = acc[i][j] * 0.125f;
            if (CAUSAL && gj > gi) v = -INFINITY;
            if (MASKED && ms[j0 + j] == 0) v = -INFINITY;
            S[((size_t)bh * SQ + gi) * sk + gj] = v;
        }
    }
}

// ------------------------ row softmax (in place) -----------------------------
template<int NITER>
__global__ __launch_bounds__(256) void softmax_rows(float* __restrict__ S)
{
    const int tid = threadIdx.x;
    float* p = S + (size_t)blockIdx.x * (NITER * 256);
    float v[NITER];
    float m = -INFINITY;
    #pragma unroll
    for (int c = 0; c < NITER; c++) { v[c] = p[tid + (c << 8)]; m = fmaxf(m, v[c]); }

    __shared__ float redm[8], reds[8];
    #pragma unroll
    for (int o = 16; o; o >>= 1) m = fmaxf(m, __shfl_xor_sync(0xffffffffu, m, o));
    if ((tid & 31) == 0) redm[tid >> 5] = m;
    __syncthreads();
    m = redm[0];
    #pragma unroll
    for (int w = 1; w < 8; w++) m = fmaxf(m, redm[w]);

    float s = 0.f;
    #pragma unroll
    for (int c = 0; c < NITER; c++) { v[c] = __expf(v[c] - m); s += v[c]; }
    #pragma unroll
    for (int o = 16; o; o >>= 1) s += __shfl_xor_sync(0xffffffffu, s, o);
    if ((tid & 31) == 0) reds[tid >> 5] = s;
    __syncthreads();
    s = reds[0];
    #pragma unroll
    for (int w = 1; w < 8; w++) s += reds[w];
    float inv = 1.f / s;
    #pragma unroll
    for (int c = 0; c < NITER; c++) p[tid + (c << 8)] = v[c] * inv;
}

// -------------------- O = P[SQ x sk] * V (per b,h; merged heads out) ---------
// grid: (SQ/64, B*H)
__global__ __launch_bounds__(256) void attn_pv(
    const float* __restrict__ P, const float* __restrict__ V,
    float* __restrict__ O, int sk)
{
    __shared__ float Ps[32][64];
    __shared__ float Vs[32][64];
    const int tid = threadIdx.x;
    const int bh = blockIdx.y, b = bh >> 4, h = bh & 15;
    const int iBase = blockIdx.x * 64;
    const int i0 = (tid >> 4) * 4, j0 = (tid & 15) * 4;

    float acc[4][4];
    #pragma unroll
    for (int i = 0; i < 4; i++)
        #pragma unroll
        for (int j = 0; j < 4; j++) acc[i][j] = 0.f;

    for (int k0 = 0; k0 < sk; k0 += 32) {
        #pragma unroll
        for (int l = 0; l < 2; l++) {
            int s = tid * 2 + l;
            int pi = s >> 3, k4 = (s & 7) * 4;
            float4 pv = *(const float4*)(P + ((size_t)bh * SQ + iBase + pi) * sk + k0 + k4);
            Ps[k4 + 0][pi] = pv.x; Ps[k4 + 1][pi] = pv.y;
            Ps[k4 + 2][pi] = pv.z; Ps[k4 + 3][pi] = pv.w;
            int vk = s >> 4, j4 = (s & 15) * 4;
            float4 vv = *(const float4*)(V + (size_t)(b * sk + k0 + vk) * DD + h * 64 + j4);
            *(float4*)&Vs[vk][j4] = vv;
        }
        __syncthreads();
        #pragma unroll
        for (int kk = 0; kk < 32; kk++) {
            float a[4], b4[4];
            *(float4*)a  = *(float4*)&Ps[kk][i0];
            *(float4*)b4 = *(float4*)&Vs[kk][j0];
            #pragma unroll
            for (int i = 0; i < 4; i++)
                #pragma unroll
                for (int j = 0; j < 4; j++)
                    acc[i][j] += a[i] * b4[j];
        }
        __syncthreads();
    }
    #pragma unroll
    for (int i = 0; i < 4; i++) {
        float4 o; o.x = acc[i][0]; o.y = acc[i][1]; o.z = acc[i][2]; o.w = acc[i][3];
        *(float4*)(O + (size_t)(b * SQ + iBase + i0 + i) * DD + h * 64 + j0) = o;
    }
}

// ----------------------- y = LN(x + r) * g + b -------------------------------
__global__ __launch_bounds__(256) void add_ln(
    const float* __restrict__ X, const float* __restrict__ R,
    const float* __restrict__ gam, const float* __restrict__ bet,
    float* __restrict__ Y)
{
    const int tid = threadIdx.x;
    const size_t base = (size_t)blockIdx.x * DD;
    float4 xv = *(const float4*)(X + base + tid * 4);
    float4 rv = *(const float4*)(R + base + tid * 4);
    float v0 = xv.x + rv.x, v1 = xv.y + rv.y, v2 = xv.z + rv.z, v3 = xv.w + rv.w;

    __shared__ float red1[8], red2[8];
    float s = v0 + v1 + v2 + v3;
    #pragma unroll
    for (int o = 16; o; o >>= 1) s += __shfl_xor_sync(0xffffffffu, s, o);
    if ((tid & 31) == 0) red1[tid >> 5] = s;
    __syncthreads();
    s = red1[0];
    #pragma unroll
    for (int w = 1; w < 8; w++) s += red1[w];
    float mu = s * (1.f / DD);

    float d0 = v0 - mu, d1 = v1 - mu, d2 = v2 - mu, d3 = v3 - mu;
    float q = d0 * d0 + d1 * d1 + d2 * d2 + d3 * d3;
    #pragma unroll
    for (int o = 16; o; o >>= 1) q += __shfl_xor_sync(0xffffffffu, q, o);
    if ((tid & 31) == 0) red2[tid >> 5] = q;
    __syncthreads();
    q = red2[0];
    #pragma unroll
    for (int w = 1; w < 8; w++) q += red2[w];
    float k = rsqrtf(q * (1.f / DD) + 1e-5f);

    float4 g4 = *(const float4*)(gam + tid * 4);
    float4 b4 = *(const float4*)(bet + tid * 4);
    float4 o;
    o.x = d0 * k * g4.x + b4.x;
    o.y = d1 * k * g4.y + b4.y;
    o.z = d2 * k * g4.z + b4.z;
    o.w = d3 * k * g4.w + b4.w;
    *(float4*)(Y + base + tid * 4) = o;
}

// ----------------------------- launcher --------------------------------------
extern "C" void kernel_launch(void* const* d_in, const int* in_sizes, int n_in,
                              void* d_out, int out_size)
{
    const float* x        = (const float*)d_in[0];
    const float* enc_o    = (const float*)d_in[1];
    const int*   enc_mask = (const int*)  d_in[2];
    const float* a1_wq = (const float*)d_in[3],  *a1_bq = (const float*)d_in[4];
    const float* a1_wk = (const float*)d_in[5],  *a1_bk = (const float*)d_in[6];
    const float* a1_wv = (const float*)d_in[7],  *a1_bv = (const float*)d_in[8];
    const float* a1_wo = (const float*)d_in[9],  *a1_bo = (const float*)d_in[10];
    const float* a2_wq = (const float*)d_in[11], *a2_bq = (const float*)d_in[12];
    const float* a2_wk = (const float*)d_in[13], *a2_bk = (const float*)d_in[14];
    const float* a2_wv = (const float*)d_in[15], *a2_bv = (const float*)d_in[16];
    const float* a2_wo = (const float*)d_in[17], *a2_bo = (const float*)d_in[18];
    const float* ff_w1 = (const float*)d_in[19], *ff_b1 = (const float*)d_in[20];
    const float* ff_w2 = (const float*)d_in[21], *ff_b2 = (const float*)d_in[22];
    const float* ln1_g = (const float*)d_in[23], *ln1_b = (const float*)d_in[24];
    const float* ln2_g = (const float*)d_in[25], *ln2_b = (const float*)d_in[26];
    const float* ln3_g = (const float*)d_in[27], *ln3_b = (const float*)d_in[28];

    float* out_x    = (float*)d_out;
    float* out_attn = out_x + (size_t)NQ * DD;

    void *pQ, *pK, *pV, *pS, *pC, *pR, *pX1, *pX2, *pFF;
    cudaGetSymbolAddress(&pQ,  g_Q);
    cudaGetSymbolAddress(&pK,  g_K);
    cudaGetSymbolAddress(&pV,  g_V);
    cudaGetSymbolAddress(&pS,  g_S);
    cudaGetSymbolAddress(&pC,  g_ctx);
    cudaGetSymbolAddress(&pR,  g_res);
    cudaGetSymbolAddress(&pX1, g_x1);
    cudaGetSymbolAddress(&pX2, g_x2);
    cudaGetSymbolAddress(&pFF, g_ffh);
    float* Q  = (float*)pQ;  float* K  = (float*)pK;  float* V  = (float*)pV;
    float* S  = (float*)pS;  float* C  = (float*)pC;  float* R  = (float*)pR;
    float* X1 = (float*)pX1; float* X2 = (float*)pX2; float* FH = (float*)pFF;

    const dim3 blk(256);

    // ---- stage 1: causal self-attention ----
    sgemm_bias<0><<<dim3(DD/128, NQ/128), blk>>>(x, a1_wq, a1_bq, Q, NQ, DD, DD);
    sgemm_bias<0><<<dim3(DD/128, NQ/128), blk>>>(x, a1_wk, a1_bk, K, NQ, DD, DD);
    sgemm_bias<0><<<dim3(DD/128, NQ/128), blk>>>(x, a1_wv, a1_bv, V, NQ, DD, DD);
    attn_scores<1,0><<<dim3(SQ/64, SQ/64, BB*HH), blk>>>(Q, K, nullptr, S, SQ);
    softmax_rows<2><<<BB*HH*SQ, blk>>>(S);
    attn_pv<<<dim3(SQ/64, BB*HH), blk>>>(S, V, C, SQ);
    sgemm_bias<0><<<dim3(DD/128, NQ/128), blk>>>(C, a1_wo, a1_bo, R, NQ, DD, DD);
    add_ln<<<NQ, blk>>>(x, R, ln1_g, ln1_b, X1);

    // ---- stage 2: cross-attention (attn probs -> output) ----
    sgemm_bias<0><<<dim3(DD/128, NQ/128),  blk>>>(X1,    a2_wq, a2_bq, Q, NQ,  DD, DD);
    sgemm_bias<0><<<dim3(DD/128, NKV/128), blk>>>(enc_o, a2_wk, a2_bk, K, NKV, DD, DD);
    sgemm_bias<0><<<dim3(DD/128, NKV/128), blk>>>(enc_o, a2_wv, a2_bv, V, NKV, DD, DD);
    attn_scores<0,1><<<dim3(SKK/64, SQ/64, BB*HH), blk>>>(Q, K, enc_mask, out_attn, SKK);
    softmax_rows<4><<<BB*HH*SQ, blk>>>(out_attn);
    attn_pv<<<dim3(SQ/64, BB*HH), blk>>>(out_attn, V, C, SKK);
    sgemm_bias<0><<<dim3(DD/128, NQ/128), blk>>>(C, a2_wo, a2_bo, R, NQ, DD, DD);
    add_ln<<<NQ, blk>>>(X1, R, ln2_g, ln2_b, X2);

    // ---- stage 3: FFN ----
    sgemm_bias<1><<<dim3(FF/128, NQ/128), blk>>>(X2, ff_w1, ff_b1, FH, NQ, FF, DD);
    sgemm_bias<0><<<dim3(DD/128, NQ/128), blk>>>(FH, ff_w2, ff_b2, R,  NQ, DD, FF);
    add_ln<<<NQ, blk>>>(X2, R, ln3_g, ln3_b, out_x);

    (void)in_sizes; (void)n_in; (void)out_size;
}

// round 4
// speedup vs baseline: 1.6402x; 1.6402x over previous
#include <cuda_runtime.h>
#include <cuda_bf16.h>
#include <cstdint>
#include <math.h>

typedef unsigned int u32;

#ifndef INFINITY
#define INFINITY (1.0f/0.0f)
#endif

#define BB 8
#define SQ 512
#define SKK 1024
#define DD 1024
#define HH 16
#define DKK 64
#define FF 4096
#define NQ (BB*SQ)     /* 4096 */
#define NKV (BB*SKK)   /* 8192 */

// ------------------------- scratch (device globals; no allocs) ---------------
__device__ float g_Q[(size_t)NQ*DD];
__device__ float g_K[(size_t)NKV*DD];
__device__ float g_V[(size_t)NKV*DD];
__device__ float g_S[(size_t)BB*HH*SQ*SQ];      // self-attn scores
__device__ float g_ctx[(size_t)NQ*DD];
__device__ float g_res[(size_t)NQ*DD];
__device__ float g_x1[(size_t)NQ*DD];
__device__ float g_x2[(size_t)NQ*DD];
__device__ float g_ffh[(size_t)NQ*FF];

// bf16 split buffers (A side up to 16M elems = FH; B side up to 4M = FFN weights)
__device__ __nv_bfloat16 g_ah[(size_t)16*1024*1024];
__device__ __nv_bfloat16 g_al[(size_t)16*1024*1024];
__device__ __nv_bfloat16 g_bh[(size_t)4*1024*1024];
__device__ __nv_bfloat16 g_bl[(size_t)4*1024*1024];

// ----------------------------- helpers ---------------------------------------
__device__ __forceinline__ u32 smem_u32(const void* p) {
    return (u32)__cvta_generic_to_shared(p);
}
__device__ __forceinline__ void ldsm_x4(u32& r0, u32& r1, u32& r2, u32& r3, u32 addr) {
    asm volatile("ldmatrix.sync.aligned.m8n8.x4.shared.b16 {%0,%1,%2,%3}, [%4];\n"
                 : "=r"(r0), "=r"(r1), "=r"(r2), "=r"(r3) : "r"(addr));
}
__device__ __forceinline__ void ldsm_x4_t(u32& r0, u32& r1, u32& r2, u32& r3, u32 addr) {
    asm volatile("ldmatrix.sync.aligned.m8n8.x4.trans.shared.b16 {%0,%1,%2,%3}, [%4];\n"
                 : "=r"(r0), "=r"(r1), "=r"(r2), "=r"(r3) : "r"(addr));
}
__device__ __forceinline__ void mma_bf16(float* c, const u32* a, const u32* b) {
    asm volatile("mma.sync.aligned.m16n8k16.row.col.f32.bf16.bf16.f32 "
                 "{%0,%1,%2,%3}, {%4,%5,%6,%7}, {%8,%9}, {%0,%1,%2,%3};\n"
                 : "+f"(c[0]), "+f"(c[1]), "+f"(c[2]), "+f"(c[3])
                 : "r"(a[0]), "r"(a[1]), "r"(a[2]), "r"(a[3]), "r"(b[0]), "r"(b[1]));
}

// ---------------- split fp32 -> (hi, lo) bf16 pair ---------------------------
__global__ __launch_bounds__(256) void split_bf16(
    const float* __restrict__ X, __nv_bfloat16* __restrict__ Hh,
    __nv_bfloat16* __restrict__ Ll, int n4)
{
    int i = blockIdx.x * blockDim.x + threadIdx.x;
    if (i >= n4) return;
    float4 v = ((const float4*)X)[i];
    __nv_bfloat16 h0 = __float2bfloat16_rn(v.x);
    __nv_bfloat16 h1 = __float2bfloat16_rn(v.y);
    __nv_bfloat16 h2 = __float2bfloat16_rn(v.z);
    __nv_bfloat16 h3 = __float2bfloat16_rn(v.w);
    __nv_bfloat16 l0 = __float2bfloat16_rn(v.x - __bfloat162float(h0));
    __nv_bfloat16 l1 = __float2bfloat16_rn(v.y - __bfloat162float(h1));
    __nv_bfloat16 l2 = __float2bfloat16_rn(v.z - __bfloat162float(h2));
    __nv_bfloat16 l3 = __float2bfloat16_rn(v.w - __bfloat162float(h3));
    ushort4 hv, lv;
    hv.x = __bfloat16_as_ushort(h0); hv.y = __bfloat16_as_ushort(h1);
    hv.z = __bfloat16_as_ushort(h2); hv.w = __bfloat16_as_ushort(h3);
    lv.x = __bfloat16_as_ushort(l0); lv.y = __bfloat16_as_ushort(l1);
    lv.z = __bfloat16_as_ushort(l2); lv.w = __bfloat16_as_ushort(l3);
    ((ushort4*)Hh)[i] = hv;
    ((ushort4*)Ll)[i] = lv;
}

// -------- tensor-core GEMM with bf16 split: C = A*B + bias (opt relu) --------
// A: MxK row-major (hi/lo), B: KxN row-major (hi/lo), C: MxN f32.
// BM=128, BN=128, BK=32; 256 thr = 8 warps (2x4), warp tile 64x32.
#define A_STRIDE 40
#define B_STRIDE 136
template<int RELU>
__global__ __launch_bounds__(256) void gemm_split(
    const __nv_bfloat16* __restrict__ Ah, const __nv_bfloat16* __restrict__ Al,
    const __nv_bfloat16* __restrict__ Bh, const __nv_bfloat16* __restrict__ Bl,
    const float* __restrict__ bias, float* __restrict__ C,
    int M, int N, int K)
{
    __shared__ __nv_bfloat16 As[2][128 * A_STRIDE];
    __shared__ __nv_bfloat16 Bs[2][32 * B_STRIDE];

    const int tid = threadIdx.x;
    const int lane = tid & 31, warp = tid >> 5;
    const int wm = warp & 1, wn = warp >> 1;
    const int mBase = blockIdx.y * 128;
    const int nBase = blockIdx.x * 128;

    const __nv_bfloat16* APs[3];
    APs[0] = Ah; APs[1] = Ah; APs[2] = Al;
    const __nv_bfloat16* BPs[3];
    BPs[0] = Bh; BPs[1] = Bl; BPs[2] = Bh;

    const int KT = K >> 5;          // 32-wide k-tiles per segment
    const int T = 3 * KT;

    // load-index precompute
    const int s0 = tid, s1 = tid + 256;
    const int a0r = s0 >> 2, a0c = (s0 & 3) * 8;
    const int a1r = s1 >> 2, a1c = (s1 & 3) * 8;
    const int b0r = s0 >> 4, b0c = (s0 & 15) * 8;
    const int b1r = s1 >> 4, b1c = (s1 & 15) * 8;

    float acc[4][4][4];
    #pragma unroll
    for (int mt = 0; mt < 4; mt++) {
        #pragma unroll
        for (int nt = 0; nt < 4; nt++) {
            #pragma unroll
            for (int i = 0; i < 4; i++) acc[mt][nt][i] = 0.f;
        }
    }

    // preload tile 0
    {
        const __nv_bfloat16* Ap = APs[0];
        const __nv_bfloat16* Bp = BPs[0];
        uint4 ra0 = *(const uint4*)(Ap + (size_t)(mBase + a0r) * K + a0c);
        uint4 ra1 = *(const uint4*)(Ap + (size_t)(mBase + a1r) * K + a1c);
        uint4 rb0 = *(const uint4*)(Bp + (size_t)b0r * N + nBase + b0c);
        uint4 rb1 = *(const uint4*)(Bp + (size_t)b1r * N + nBase + b1c);
        *(uint4*)&As[0][a0r * A_STRIDE + a0c] = ra0;
        *(uint4*)&As[0][a1r * A_STRIDE + a1c] = ra1;
        *(uint4*)&Bs[0][b0r * B_STRIDE + b0c] = rb0;
        *(uint4*)&Bs[0][b1r * B_STRIDE + b1c] = rb1;
    }
    __syncthreads();

    for (int tt = 0; tt < T; tt++) {
        const int buf = tt & 1;
        uint4 ra0, ra1, rb0, rb1;
        const bool hasNext = (tt + 1 < T);
        if (hasNext) {
            int nt_ = tt + 1;
            int seg = nt_ / KT;
            int kk = (nt_ - seg * KT) << 5;
            const __nv_bfloat16* Ap = APs[seg];
            const __nv_bfloat16* Bp = BPs[seg];
            ra0 = *(const uint4*)(Ap + (size_t)(mBase + a0r) * K + kk + a0c);
            ra1 = *(const uint4*)(Ap + (size_t)(mBase + a1r) * K + kk + a1c);
            rb0 = *(const uint4*)(Bp + (size_t)(kk + b0r) * N + nBase + b0c);
            rb1 = *(const uint4*)(Bp + (size_t)(kk + b1r) * N + nBase + b1c);
        }

        // compute current tile
        #pragma unroll
        for (int ks = 0; ks < 2; ks++) {
            const int kb = ks * 16;
            u32 a[4][4];
            #pragma unroll
            for (int mt = 0; mt < 4; mt++) {
                int row = wm * 64 + mt * 16 + (lane & 15);
                int col = kb + (lane >> 4) * 8;
                ldsm_x4(a[mt][0], a[mt][1], a[mt][2], a[mt][3],
                        smem_u32(&As[buf][row * A_STRIDE + col]));
            }
            u32 b[4][2];
            #pragma unroll
            for (int np = 0; np < 2; np++) {
                int krow = kb + (lane & 7) + ((lane >> 3) & 1) * 8;
                int col = wn * 32 + np * 16 + (lane >> 4) * 8;
                u32 r0, r1, r2, r3;
                ldsm_x4_t(r0, r1, r2, r3, smem_u32(&Bs[buf][krow * B_STRIDE + col]));
                b[np * 2][0] = r0;     b[np * 2][1] = r1;
                b[np * 2 + 1][0] = r2; b[np * 2 + 1][1] = r3;
            }
            #pragma unroll
            for (int mt = 0; mt < 4; mt++) {
                #pragma unroll
                for (int nt = 0; nt < 4; nt++) {
                    mma_bf16(acc[mt][nt], a[mt], b[nt]);
                }
            }
        }

        if (hasNext) {
            const int nb = (tt + 1) & 1;
            *(uint4*)&As[nb][a0r * A_STRIDE + a0c] = ra0;
            *(uint4*)&As[nb][a1r * A_STRIDE + a1c] = ra1;
            *(uint4*)&Bs[nb][b0r * B_STRIDE + b0c] = rb0;
            *(uint4*)&Bs[nb][b1r * B_STRIDE + b1c] = rb1;
            __syncthreads();
        }
    }

    // epilogue
    const int g = lane >> 2, tig = lane & 3;
    #pragma unroll
    for (int mt = 0; mt < 4; mt++) {
        int r0 = mBase + wm * 64 + mt * 16 + g;
        #pragma unroll
        for (int nt = 0; nt < 4; nt++) {
            int c0 = nBase + wn * 32 + nt * 8 + tig * 2;
            float b0 = bias[c0], b1 = bias[c0 + 1];
            float v0 = acc[mt][nt][0] + b0;
            float v1 = acc[mt][nt][1] + b1;
            float v2 = acc[mt][nt][2] + b0;
            float v3 = acc[mt][nt][3] + b1;
            if (RELU) {
                v0 = fmaxf(v0, 0.f); v1 = fmaxf(v1, 0.f);
                v2 = fmaxf(v2, 0.f); v3 = fmaxf(v3, 0.f);
            }
            C[(size_t)r0 * N + c0] = v0;
            C[(size_t)r0 * N + c0 + 1] = v1;
            C[(size_t)(r0 + 8) * N + c0] = v2;
            C[(size_t)(r0 + 8) * N + c0 + 1] = v3;
        }
    }
}

// ------------- attention scores: S = scale * Q K^T (+ causal / kv-mask) ------
template<int CAUSAL, int MASKED>
__global__ __launch_bounds__(256) void attn_scores(
    const float* __restrict__ Q, const float* __restrict__ Kg,
    const int* __restrict__ mask, float* __restrict__ S, int sk)
{
    __shared__ float Qs[64][65];
    __shared__ float Ks[64][65];
    __shared__ int   ms[64];
    const int tid = threadIdx.x;
    const int bh = blockIdx.z, b = bh >> 4, h = bh & 15;
    const int iBase = blockIdx.y * 64, jBase = blockIdx.x * 64;

    if (CAUSAL && jBase > iBase + 63) {
        for (int s = tid; s < 64 * 64; s += 256) {
            int i = s >> 6, j = s & 63;
            S[((size_t)bh * SQ + iBase + i) * sk + jBase + j] = -INFINITY;
        }
        return;
    }

    for (int s = tid; s < 64 * 16; s += 256) {
        int r = s >> 4, d4 = (s & 15) * 4;
        float4 qv = *(const float4*)(Q + (size_t)(b * SQ + iBase + r) * DD + h * 64 + d4);
        Qs[r][d4 + 0] = qv.x; Qs[r][d4 + 1] = qv.y; Qs[r][d4 + 2] = qv.z; Qs[r][d4 + 3] = qv.w;
        float4 kv = *(const float4*)(Kg + (size_t)(b * sk + jBase + r) * DD + h * 64 + d4);
        Ks[r][d4 + 0] = kv.x; Ks[r][d4 + 1] = kv.y; Ks[r][d4 + 2] = kv.z; Ks[r][d4 + 3] = kv.w;
    }
    if (MASKED && tid < 64) ms[tid] = mask[b * SKK + jBase + tid];
    __syncthreads();

    const int i0 = (tid >> 4) * 4, j0 = (tid & 15) * 4;
    float acc[4][4];
    #pragma unroll
    for (int i = 0; i < 4; i++) {
        #pragma unroll
        for (int j = 0; j < 4; j++) acc[i][j] = 0.f;
    }

    #pragma unroll 16
    for (int d = 0; d < 64; d++) {
        float a[4], bv[4];
        #pragma unroll
        for (int i = 0; i < 4; i++) a[i] = Qs[i0 + i][d];
        #pragma unroll
        for (int j = 0; j < 4; j++) bv[j] = Ks[j0 + j][d];
        #pragma unroll
        for (int i = 0; i < 4; i++) {
            #pragma unroll
            for (int j = 0; j < 4; j++) acc[i][j] += a[i] * bv[j];
        }
    }

    #pragma unroll
    for (int i = 0; i < 4; i++) {
        int gi = iBase + i0 + i;
        #pragma unroll
        for (int j = 0; j < 4; j++) {
            int gj = jBase + j0 + j;
            float v = acc[i][j] * 0.125f;
            if (CAUSAL && gj > gi) v = -INFINITY;
            if (MASKED && ms[j0 + j] == 0) v = -INFINITY;
            S[((size_t)bh * SQ + gi) * sk + gj] = v;
        }
    }
}

// ------------------------ row softmax (in place) -----------------------------
template<int NITER>
__global__ __launch_bounds__(256) void softmax_rows(float* __restrict__ S)
{
    const int tid = threadIdx.x;
    float* p = S + (size_t)blockIdx.x * (NITER * 256);
    float v[NITER];
    float m = -INFINITY;
    #pragma unroll
    for (int c = 0; c < NITER; c++) { v[c] = p[tid + (c << 8)]; m = fmaxf(m, v[c]); }

    __shared__ float redm[8], reds[8];
    #pragma unroll
    for (int o = 16; o; o >>= 1) m = fmaxf(m, __shfl_xor_sync(0xffffffffu, m, o));
    if ((tid & 31) == 0) redm[tid >> 5] = m;
    __syncthreads();
    m = redm[0];
    #pragma unroll
    for (int w = 1; w < 8; w++) m = fmaxf(m, redm[w]);

    float s = 0.f;
    #pragma unroll
    for (int c = 0; c < NITER; c++) { v[c] = __expf(v[c] - m); s += v[c]; }
    #pragma unroll
    for (int o = 16; o; o >>= 1) s += __shfl_xor_sync(0xffffffffu, s, o);
    if ((tid & 31) == 0) reds[tid >> 5] = s;
    __syncthreads();
    s = reds[0];
    #pragma unroll
    for (int w = 1; w < 8; w++) s += reds[w];
    float inv = 1.f / s;
    #pragma unroll
    for (int c = 0; c < NITER; c++) p[tid + (c << 8)] = v[c] * inv;
}

// -------------------- O = P[SQ x sk] * V (per b,h; merged heads out) ---------
__global__ __launch_bounds__(256) void attn_pv(
    const float* __restrict__ P, const float* __restrict__ V,
    float* __restrict__ O, int sk)
{
    __shared__ float Ps[32][64];
    __shared__ float Vs[32][64];
    const int tid = threadIdx.x;
    const int bh = blockIdx.y, b = bh >> 4, h = bh & 15;
    const int iBase = blockIdx.x * 64;
    const int i0 = (tid >> 4) * 4, j0 = (tid & 15) * 4;

    float acc[4][4];
    #pragma unroll
    for (int i = 0; i < 4; i++) {
        #pragma unroll
        for (int j = 0; j < 4; j++) acc[i][j] = 0.f;
    }

    for (int k0 = 0; k0 < sk; k0 += 32) {
        #pragma unroll
        for (int l = 0; l < 2; l++) {
            int s = tid * 2 + l;
            int pi = s >> 3, k4 = (s & 7) * 4;
            float4 pv = *(const float4*)(P + ((size_t)bh * SQ + iBase + pi) * sk + k0 + k4);
            Ps[k4 + 0][pi] = pv.x; Ps[k4 + 1][pi] = pv.y;
            Ps[k4 + 2][pi] = pv.z; Ps[k4 + 3][pi] = pv.w;
            int vk = s >> 4, j4 = (s & 15) * 4;
            float4 vv = *(const float4*)(V + (size_t)(b * sk + k0 + vk) * DD + h * 64 + j4);
            *(float4*)&Vs[vk][j4] = vv;
        }
        __syncthreads();
        #pragma unroll
        for (int kk = 0; kk < 32; kk++) {
            float a[4], bv[4];
            *(float4*)a  = *(float4*)&Ps[kk][i0];
            *(float4*)bv = *(float4*)&Vs[kk][j0];
            #pragma unroll
            for (int i = 0; i < 4; i++) {
                #pragma unroll
                for (int j = 0; j < 4; j++) acc[i][j] += a[i] * bv[j];
            }
        }
        __syncthreads();
    }
    #pragma unroll
    for (int i = 0; i < 4; i++) {
        float4 o; o.x = acc[i][0]; o.y = acc[i][1]; o.z = acc[i][2]; o.w = acc[i][3];
        *(float4*)(O + (size_t)(b * SQ + iBase + i0 + i) * DD + h * 64 + j0) = o;
    }
}

// ----------------------- y = LN(x + r) * g + b -------------------------------
__global__ __launch_bounds__(256) void add_ln(
    const float* __restrict__ X, const float* __restrict__ R,
    const float* __restrict__ gam, const float* __restrict__ bet,
    float* __restrict__ Y)
{
    const int tid = threadIdx.x;
    const size_t base = (size_t)blockIdx.x * DD;
    float4 xv = *(const float4*)(X + base + tid * 4);
    float4 rv = *(const float4*)(R + base + tid * 4);
    float v0 = xv.x + rv.x, v1 = xv.y + rv.y, v2 = xv.z + rv.z, v3 = xv.w + rv.w;

    __shared__ float red1[8], red2[8];
    float s = v0 + v1 + v2 + v3;
    #pragma unroll
    for (int o = 16; o; o >>= 1) s += __shfl_xor_sync(0xffffffffu, s, o);
    if ((tid & 31) == 0) red1[tid >> 5] = s;
    __syncthreads();
    s = red1[0];
    #pragma unroll
    for (int w = 1; w < 8; w++) s += red1[w];
    float mu = s * (1.f / DD);

    float d0 = v0 - mu, d1 = v1 - mu, d2 = v2 - mu, d3 = v3 - mu;
    float q = d0 * d0 + d1 * d1 + d2 * d2 + d3 * d3;
    #pragma unroll
    for (int o = 16; o; o >>= 1) q += __shfl_xor_sync(0xffffffffu, q, o);
    if ((tid & 31) == 0) red2[tid >> 5] = q;
    __syncthreads();
    q = red2[0];
    #pragma unroll
    for (int w = 1; w < 8; w++) q += red2[w];
    float k = rsqrtf(q * (1.f / DD) + 1e-5f);

    float4 g4 = *(const float4*)(gam + tid * 4);
    float4 b4 = *(const float4*)(bet + tid * 4);
    float4 o;
    o.x = d0 * k * g4.x + b4.x;
    o.y = d1 * k * g4.y + b4.y;
    o.z = d2 * k * g4.z + b4.z;
    o.w = d3 * k * g4.w + b4.w;
    *(float4*)(Y + base + tid * 4) = o;
}

// ----------------------------- launcher --------------------------------------
extern "C" void kernel_launch(void* const* d_in, const int* in_sizes, int n_in,
                              void* d_out, int out_size)
{
    const float* x        = (const float*)d_in[0];
    const float* enc_o    = (const float*)d_in[1];
    const int*   enc_mask = (const int*)  d_in[2];
    const float* a1_wq = (const float*)d_in[3],  *a1_bq = (const float*)d_in[4];
    const float* a1_wk = (const float*)d_in[5],  *a1_bk = (const float*)d_in[6];
    const float* a1_wv = (const float*)d_in[7],  *a1_bv = (const float*)d_in[8];
    const float* a1_wo = (const float*)d_in[9],  *a1_bo = (const float*)d_in[10];
    const float* a2_wq = (const float*)d_in[11], *a2_bq = (const float*)d_in[12];
    const float* a2_wk = (const float*)d_in[13], *a2_bk = (const float*)d_in[14];
    const float* a2_wv = (const float*)d_in[15], *a2_bv = (const float*)d_in[16];
    const float* a2_wo = (const float*)d_in[17], *a2_bo = (const float*)d_in[18];
    const float* ff_w1 = (const float*)d_in[19], *ff_b1 = (const float*)d_in[20];
    const float* ff_w2 = (const float*)d_in[21], *ff_b2 = (const float*)d_in[22];
    const float* ln1_g = (const float*)d_in[23], *ln1_b = (const float*)d_in[24];
    const float* ln2_g = (const float*)d_in[25], *ln2_b = (const float*)d_in[26];
    const float* ln3_g = (const float*)d_in[27], *ln3_b = (const float*)d_in[28];

    float* out_x    = (float*)d_out;
    float* out_attn = out_x + (size_t)NQ * DD;

    void *pQ, *pK, *pV, *pS, *pC, *pR, *pX1, *pX2, *pFF, *pAH, *pAL, *pBH, *pBL;
    cudaGetSymbolAddress(&pQ,  g_Q);
    cudaGetSymbolAddress(&pK,  g_K);
    cudaGetSymbolAddress(&pV,  g_V);
    cudaGetSymbolAddress(&pS,  g_S);
    cudaGetSymbolAddress(&pC,  g_ctx);
    cudaGetSymbolAddress(&pR,  g_res);
    cudaGetSymbolAddress(&pX1, g_x1);
    cudaGetSymbolAddress(&pX2, g_x2);
    cudaGetSymbolAddress(&pFF, g_ffh);
    cudaGetSymbolAddress(&pAH, g_ah);
    cudaGetSymbolAddress(&pAL, g_al);
    cudaGetSymbolAddress(&pBH, g_bh);
    cudaGetSymbolAddress(&pBL, g_bl);
    float* Q  = (float*)pQ;  float* K  = (float*)pK;  float* V  = (float*)pV;
    float* S  = (float*)pS;  float* C  = (float*)pC;  float* R  = (float*)pR;
    float* X1 = (float*)pX1; float* X2 = (float*)pX2; float* FH = (float*)pFF;
    __nv_bfloat16* AH = (__nv_bfloat16*)pAH; __nv_bfloat16* AL = (__nv_bfloat16*)pAL;
    __nv_bfloat16* BH = (__nv_bfloat16*)pBH; __nv_bfloat16* BL = (__nv_bfloat16*)pBL;

    const dim3 blk(256);

    const size_t NW  = (size_t)DD * DD;      // 1M (attn weights)
    const size_t NA4 = (size_t)NQ * DD;      // 4M
    const size_t NA8 = (size_t)NKV * DD;     // 8M

    // ---- stage 1: causal self-attention ----
    split_bf16<<<(int)(NA4/4 + 255)/256, 256>>>(x, AH, AL, (int)(NA4/4));
    split_bf16<<<(int)(NW/4 + 255)/256, 256>>>(a1_wq, BH, BL, (int)(NW/4));
    gemm_split<0><<<dim3(DD/128, NQ/128), blk>>>(AH, AL, BH, BL, a1_bq, Q, NQ, DD, DD);
    split_bf16<<<(int)(NW/4 + 255)/256, 256>>>(a1_wk, BH, BL, (int)(NW/4));
    gemm_split<0><<<dim3(DD/128, NQ/128), blk>>>(AH, AL, BH, BL, a1_bk, K, NQ, DD, DD);
    split_bf16<<<(int)(NW/4 + 255)/256, 256>>>(a1_wv, BH, BL, (int)(NW/4));
    gemm_split<0><<<dim3(DD/128, NQ/128), blk>>>(AH, AL, BH, BL, a1_bv, V, NQ, DD, DD);
    attn_scores<1,0><<<dim3(SQ/64, SQ/64, BB*HH), blk>>>(Q, K, (const int*)0, S, SQ);
    softmax_rows<2><<<BB*HH*SQ, blk>>>(S);
    attn_pv<<<dim3(SQ/64, BB*HH), blk>>>(S, V, C, SQ);
    split_bf16<<<(int)(NA4/4 + 255)/256, 256>>>(C, AH, AL, (int)(NA4/4));
    split_bf16<<<(int)(NW/4 + 255)/256, 256>>>(a1_wo, BH, BL, (int)(NW/4));
    gemm_split<0><<<dim3(DD/128, NQ/128), blk>>>(AH, AL, BH, BL, a1_bo, R, NQ, DD, DD);
    add_ln<<<NQ, blk>>>(x, R, ln1_g, ln1_b, X1);

    // ---- stage 2: cross-attention (attn probs -> output) ----
    split_bf16<<<(int)(NA4/4 + 255)/256, 256>>>(X1, AH, AL, (int)(NA4/4));
    split_bf16<<<(int)(NW/4 + 255)/256, 256>>>(a2_wq, BH, BL, (int)(NW/4));
    gemm_split<0><<<dim3(DD/128, NQ/128), blk>>>(AH, AL, BH, BL, a2_bq, Q, NQ, DD, DD);
    split_bf16<<<(int)(NA8/4 + 255)/256, 256>>>(enc_o, AH, AL, (int)(NA8/4));
    split_bf16<<<(int)(NW/4 + 255)/256, 256>>>(a2_wk, BH, BL, (int)(NW/4));
    gemm_split<0><<<dim3(DD/128, NKV/128), blk>>>(AH, AL, BH, BL, a2_bk, K, NKV, DD, DD);
    split_bf16<<<(int)(NW/4 + 255)/256, 256>>>(a2_wv, BH, BL, (int)(NW/4));
    gemm_split<0><<<dim3(DD/128, NKV/128), blk>>>(AH, AL, BH, BL, a2_bv, V, NKV, DD, DD);
    attn_scores<0,1><<<dim3(SKK/64, SQ/64, BB*HH), blk>>>(Q, K, enc_mask, out_attn, SKK);
    softmax_rows<4><<<BB*HH*SQ, blk>>>(out_attn);
    attn_pv<<<dim3(SQ/64, BB*HH), blk>>>(out_attn, V, C, SKK);
    split_bf16<<<(int)(NA4/4 + 255)/256, 256>>>(C, AH, AL, (int)(NA4/4));
    split_bf16<<<(int)(NW/4 + 255)/256, 256>>>(a2_wo, BH, BL, (int)(NW/4));
    gemm_split<0><<<dim3(DD/128, NQ/128), blk>>>(AH, AL, BH, BL, a2_bo, R, NQ, DD, DD);
    add_ln<<<NQ, blk>>>(X1, R, ln2_g, ln2_b, X2);

    // ---- stage 3: FFN ----
    split_bf16<<<(int)(NA4/4 + 255)/256, 256>>>(X2, AH, AL, (int)(NA4/4));
    split_bf16<<<(int)((size_t)DD*FF/4 + 255)/256, 256>>>(ff_w1, BH, BL, (int)((size_t)DD*FF/4));
    gemm_split<1><<<dim3(FF/128, NQ/128), blk>>>(AH, AL, BH, BL, ff_b1, FH, NQ, FF, DD);
    split_bf16<<<(int)((size_t)NQ*FF/4 + 255)/256, 256>>>(FH, AH, AL, (int)((size_t)NQ*FF/4));
    split_bf16<<<(int)((size_t)FF*DD/4 + 255)/256, 256>>>(ff_w2, BH, BL, (int)((size_t)FF*DD/4));
    gemm_split<0><<<dim3(DD/128, NQ/128), blk>>>(AH, AL, BH, BL, ff_b2, R, NQ, DD, FF);
    add_ln<<<NQ, blk>>>(X2, R, ln3_g, ln3_b, out_x);

    (void)in_sizes; (void)n_in; (void)out_size;
}